// round 3
// baseline (speedup 1.0000x reference)
#include <cuda_runtime.h>
#include <math.h>

#define BB 64
#define FF 512
#define EE 256
#define HH 8
#define DD 32
#define LL 4

// Precomputed collapsed vectors + handshake flags (device globals; zero-init)
__device__ float g_kw[EE];   // emb_w @ k_w
__device__ float g_vw[EE];   // emb_w @ v_w
__device__ float g_vb[EE];   // emb_b @ v_w + v_b
__device__ float g_qv[EE];   // emb_b @ q_w + q_b
__device__ unsigned int g_flag = 0;   // producer blocks done (target 32)
__device__ unsigned int g_done = 0;   // consumer blocks done (target 64)

__device__ __forceinline__ float ex2f(float x) {
    float y;
    asm("ex2.approx.ftz.f32 %0, %1;" : "=f"(y) : "f"(x));
    return y;
}

// ---------------------------------------------------------------------------
// Single fused kernel. grid = 64 (one block per batch), block = 256.
// Blocks 0..31 additionally each compute one precompute unit
// (matrix m = b>>3, column-group grp = b&7) and release it via a
// fence + single atomicAdd. All blocks overlap their feature prologue
// with the precompute, then spin on the flag (single-wave residency:
// 64 blocks <= 148 SMs, so no deadlock is possible).
// ---------------------------------------------------------------------------
__global__ void __launch_bounds__(256, 1)
fused_kernel(const float* __restrict__ features,
             const float* __restrict__ emb_w,
             const float* __restrict__ emb_b,
             const float* __restrict__ q_w,
             const float* __restrict__ q_b,
             const float* __restrict__ k_w,
             const float* __restrict__ v_w,
             const float* __restrict__ v_b,
             const float* __restrict__ attn_w,
             const float* __restrict__ attn_b,
             float* __restrict__ out) {
    __shared__ float s_pre[8][32];
    __shared__ float sx[FF];
    __shared__ float rS[8], rMax[8], rMin[8];
    __shared__ float s_ox[HH], s_hc[HH];

    const int b    = blockIdx.x;
    const int t    = threadIdx.x;       // 0..255
    const int warp = t >> 5;
    const int lane = t & 31;

    // ---- Producer partial dot (blocks 0..31): warp = row chunk ----
    if (b < 32) {
        const int m   = b >> 3;         // 0:kw 1:vw 2:vb 3:qv
        const int grp = b & 7;
        const int col = grp * 32 + lane;
        const float* vecsrc = (m <= 1) ? emb_w : emb_b;
        const float* mat    = (m == 0) ? k_w : (m == 3 ? q_w : v_w);
        float ev = vecsrc[warp * 32 + lane];
        const float* mp = mat + (warp * 32) * EE + col;
        float acc = 0.f;
        #pragma unroll
        for (int e = 0; e < 32; e++)
            acc = fmaf(__shfl_sync(0xffffffffu, ev, e), mp[e * EE], acc);
        s_pre[warp][lane] = acc;
    }

    // ---- Feature prologue (every block; overlaps producer latency) ----
    float2 xv = reinterpret_cast<const float2*>(features + b * FF)[t];
    float aw = attn_w[warp * DD + lane];
    float ab = attn_b[0];
    sx[2 * t]     = xv.x;
    sx[2 * t + 1] = xv.y;

    float lsum = xv.x + xv.y;
    float lmax = fmaxf(xv.x, xv.y);
    float lmin = fminf(xv.x, xv.y);
    #pragma unroll
    for (int o = 16; o > 0; o >>= 1) {
        lsum += __shfl_xor_sync(0xffffffffu, lsum, o);
        lmax  = fmaxf(lmax, __shfl_xor_sync(0xffffffffu, lmax, o));
        lmin  = fminf(lmin, __shfl_xor_sync(0xffffffffu, lmin, o));
    }
    if (lane == 0) { rS[warp] = lsum; rMax[warp] = lmax; rMin[warp] = lmin; }

    __syncthreads();   // (A) s_pre + sx + rS ready

    // ---- Producer final reduce + publish ----
    if (b < 32 && t < 32) {
        const int m   = b >> 3;
        const int grp = b & 7;
        const int col = grp * 32 + lane;
        float a = 0.f;
        #pragma unroll
        for (int r = 0; r < 8; r++) a += s_pre[r][lane];
        if (m == 2) a += v_b[col];
        if (m == 3) a += q_b[col];
        float* dst = (m == 0) ? g_kw : (m == 1) ? g_vw : (m == 2) ? g_vb : g_qv;
        dst[col] = a;
    }

    // ---- Block-level x stats + register cache (independent of g_*) ----
    float S = 0.f, xmax = -1e30f, xmin = 1e30f;
    #pragma unroll
    for (int w = 0; w < 8; w++) {
        S += rS[w]; xmax = fmaxf(xmax, rMax[w]); xmin = fminf(xmin, rMin[w]);
    }
    float xr[FF / 32];
    #pragma unroll
    for (int i = 0; i < FF / 32; i++) xr[i] = sx[lane + i * 32];

    // ---- Release (producers) then acquire (everyone) ----
    __threadfence();
    __syncthreads();   // (B) producer g_* stores globally ordered before atomic
    if (b < 32 && t == 0) atomicAdd(&g_flag, 1u);
    if (t == 0) {
        volatile unsigned int* f = &g_flag;
        while (*f < 32u) { }
    }
    __syncthreads();   // (C) whole block past the gate
    __threadfence();

    // ---- Per-head scalar constants via warp butterfly dot (D == 32) ----
    const int hi = warp * DD + lane;
    float kw = __ldcg(&g_kw[hi]);
    float vw = __ldcg(&g_vw[hi]);
    float vb = __ldcg(&g_vb[hi]);
    float qv = __ldcg(&g_qv[hi]);

    const float scale = 0.17677669529663687f;      // 1/sqrt(32)
    float A0 = qv * kw, P = vw * kw, R = vb * kw, VA = vw * aw, VB = vb * aw;
    #pragma unroll
    for (int o = 16; o > 0; o >>= 1) {
        A0 += __shfl_xor_sync(0xffffffffu, A0, o);
        P  += __shfl_xor_sync(0xffffffffu, P,  o);
        R  += __shfl_xor_sync(0xffffffffu, R,  o);
        VA += __shfl_xor_sync(0xffffffffu, VA, o);
        VB += __shfl_xor_sync(0xffffffffu, VB, o);
    }
    A0 *= scale; P *= scale; R *= scale;

    // ---- L-step scalar softmax recursion (warp-local) ----
    const float L2E = 1.4426950408889634f;
    float alpha = A0;
    float m = 0.f;
    #pragma unroll
    for (int it = 0; it < LL; it++) {
        float a2 = alpha * L2E;
        float M2 = (alpha >= 0.f) ? a2 * xmax : a2 * xmin;   // exact max logit
        float sw = 0.f, sxw = 0.f;
        #pragma unroll
        for (int i = 0; i < FF / 32; i++) {
            float w = ex2f(fmaf(a2, xr[i], -M2));
            sw += w;
            sxw = fmaf(xr[i], w, sxw);
        }
        #pragma unroll
        for (int o = 16; o > 0; o >>= 1) {
            sw  += __shfl_xor_sync(0xffffffffu, sw,  o);
            sxw += __shfl_xor_sync(0xffffffffu, sxw, o);
        }
        m = __fdividef(sxw, sw);
        alpha = fmaf(m, P, R);
    }

    if (lane == 0) {
        s_ox[warp] = fmaf(m, VA, VB);                          // Qc contribution
        s_hc[warp] = fmaf(S - m, VA, (float)(FF - 1) * VB);    // (v_sum - Qc)
    }
    __syncthreads();   // (D) all threads past g_* reads; s_ox/s_hc ready

    float ox = ab, cc = ab;
    #pragma unroll
    for (int hh = 0; hh < HH; hh++) { ox += s_ox[hh]; cc += s_hc[hh]; }

    out[b * FF + t]                 = ox;
    out[b * FF + t + 256]           = ox;
    out[BB * FF + b * FF + t]       = cc;
    out[BB * FF + b * FF + t + 256] = cc;

    // ---- Last block resets the flags for the next graph replay ----
    if (t == 0) {
        __threadfence();
        unsigned int prev = atomicAdd(&g_done, 1u);
        if (prev == BB - 1) {
            g_flag = 0u;
            g_done = 0u;
            __threadfence();
        }
    }
}

extern "C" void kernel_launch(void* const* d_in, const int* in_sizes, int n_in,
                              void* d_out, int out_size) {
    const float* features = (const float*)d_in[0];
    const float* emb_w    = (const float*)d_in[1];
    const float* emb_b    = (const float*)d_in[2];
    const float* q_w      = (const float*)d_in[3];
    const float* q_b      = (const float*)d_in[4];
    const float* k_w      = (const float*)d_in[5];
    // d_in[6] = k_b: cancels in softmax, unused
    const float* v_w      = (const float*)d_in[7];
    const float* v_b      = (const float*)d_in[8];
    const float* attn_w   = (const float*)d_in[9];
    const float* attn_b   = (const float*)d_in[10];
    float* out = (float*)d_out;

    fused_kernel<<<BB, 256>>>(features, emb_w, emb_b, q_w, q_b, k_w,
                              v_w, v_b, attn_w, attn_b, out);
}

// round 4
// speedup vs baseline: 1.2610x; 1.2610x over previous
#include <cuda_runtime.h>
#include <math.h>

#define BB 64
#define FF 512
#define EE 256
#define HH 8
#define DD 32
#define LL 4

// Precomputed collapsed vectors (device globals: no allocation allowed)
__device__ float g_kw[EE];   // emb_w @ k_w
__device__ float g_vw[EE];   // emb_w @ v_w
__device__ float g_vb[EE];   // emb_b @ v_w + v_b
__device__ float g_qv[EE];   // emb_b @ q_w + q_b

__device__ __forceinline__ float ex2f(float x) {
    float y;
    asm("ex2.approx.ftz.f32 %0, %1;" : "=f"(y) : "f"(x));
    return y;
}

// ---------------------------------------------------------------------------
// Kernel A: 4 vector-matrix products, each 256-dot split across 8 warps
// (32 fully-unrolled loads each -> one DRAM/L2 round-trip).
// grid = 32 (4 matrices x 8 col-groups), 256 threads.
// ---------------------------------------------------------------------------
__global__ void __launch_bounds__(256)
precompute_kernel(const float* __restrict__ emb_w,
                  const float* __restrict__ emb_b,
                  const float* __restrict__ q_w,
                  const float* __restrict__ q_b,
                  const float* __restrict__ k_w,
                  const float* __restrict__ v_w,
                  const float* __restrict__ v_b) {
    const int m     = blockIdx.x >> 3;          // 0:kw 1:vw 2:vb 3:qv
    const int grp   = blockIdx.x & 7;           // column group (32 cols)
    const int lane  = threadIdx.x & 31;
    const int chunk = threadIdx.x >> 5;         // row chunk == warp id
    const int col   = grp * 32 + lane;

    const float* vecsrc = (m <= 1) ? emb_w : emb_b;
    const float* mat    = (m == 0) ? k_w : (m == 3 ? q_w : v_w);

    float ev = vecsrc[chunk * 32 + lane];
    const float* mp = mat + (chunk * 32) * EE + col;

    float acc = 0.f;
    #pragma unroll
    for (int e = 0; e < 32; e++)
        acc = fmaf(__shfl_sync(0xffffffffu, ev, e), mp[e * EE], acc);

    __shared__ float s[8][32];
    s[chunk][lane] = acc;
    __syncthreads();

    if (threadIdx.x < 32) {
        float a = 0.f;
        #pragma unroll
        for (int r = 0; r < 8; r++) a += s[r][lane];
        if (m == 2) a += v_b[col];
        if (m == 3) a += q_b[col];
        float* dst = (m == 0) ? g_kw : (m == 1) ? g_vw : (m == 2) ? g_vb : g_qv;
        dst[col] = a;
    }
}

// ---------------------------------------------------------------------------
// Kernel B: per-batch block (grid = 64), 256 threads = 8 warps = 8 heads.
// Each warp loads the ENTIRE x_b[512] into registers (16 per lane, coalesced),
// so sum/max/min and the whole L=4 recursion are warp-local: zero smem
// traffic and zero block syncs until the final head combine.
// ---------------------------------------------------------------------------
__global__ void __launch_bounds__(256, 8)
attn_kernel(const float* __restrict__ features,
            const float* __restrict__ attn_w,
            const float* __restrict__ attn_b,
            float* __restrict__ out) {
    __shared__ float s_ox[HH], s_hc[HH];

    const int b    = blockIdx.x;
    const int t    = threadIdx.x;       // 0..255
    const int warp = t >> 5;
    const int lane = t & 31;

    // ---- Each warp loads the full feature vector: xr[i] = x[lane + 32i] ----
    const float* xb = features + b * FF;
    float xr[FF / 32];
    #pragma unroll
    for (int i = 0; i < FF / 32; i++) xr[i] = xb[lane + i * 32];

    // ---- Head constant loads (overlap with feature load latency) ----
    const int hi = warp * DD + lane;
    float kw = g_kw[hi];
    float vw = g_vw[hi];
    float vb = g_vb[hi];
    float qv = g_qv[hi];
    float aw = attn_w[hi];
    float ab = attn_b[0];

    // ---- Warp-local stats over the full vector ----
    float S = 0.f, xmax = -1e30f, xmin = 1e30f;
    #pragma unroll
    for (int i = 0; i < FF / 32; i++) {
        S += xr[i];
        xmax = fmaxf(xmax, xr[i]);
        xmin = fminf(xmin, xr[i]);
    }

    // ---- Head scalars ----
    const float scale = 0.17677669529663687f;      // 1/sqrt(32)
    float A0 = qv * kw, P = vw * kw, R = vb * kw, VA = vw * aw, VB = vb * aw;

    // ---- One interleaved butterfly for all 8 reductions ----
    #pragma unroll
    for (int o = 16; o > 0; o >>= 1) {
        S    += __shfl_xor_sync(0xffffffffu, S,    o);
        xmax  = fmaxf(xmax, __shfl_xor_sync(0xffffffffu, xmax, o));
        xmin  = fminf(xmin, __shfl_xor_sync(0xffffffffu, xmin, o));
        A0   += __shfl_xor_sync(0xffffffffu, A0,   o);
        P    += __shfl_xor_sync(0xffffffffu, P,    o);
        R    += __shfl_xor_sync(0xffffffffu, R,    o);
        VA   += __shfl_xor_sync(0xffffffffu, VA,   o);
        VB   += __shfl_xor_sync(0xffffffffu, VB,   o);
    }
    A0 *= scale; P *= scale; R *= scale;

    // ---- L-step scalar softmax recursion (fully warp-local) ----
    const float L2E = 1.4426950408889634f;
    float alpha = A0;
    float m = 0.f;
    #pragma unroll
    for (int it = 0; it < LL; it++) {
        float a2 = alpha * L2E;
        float M2 = (alpha >= 0.f) ? a2 * xmax : a2 * xmin;   // exact max logit
        float sw = 0.f, sxw = 0.f;
        #pragma unroll
        for (int i = 0; i < FF / 32; i++) {
            float w = ex2f(fmaf(a2, xr[i], -M2));
            sw += w;
            sxw = fmaf(xr[i], w, sxw);
        }
        #pragma unroll
        for (int o = 16; o > 0; o >>= 1) {
            sw  += __shfl_xor_sync(0xffffffffu, sw,  o);
            sxw += __shfl_xor_sync(0xffffffffu, sxw, o);
        }
        m = __fdividef(sxw, sw);
        alpha = fmaf(m, P, R);
    }

    if (lane == 0) {
        s_ox[warp] = fmaf(m, VA, VB);                          // Qc contribution
        s_hc[warp] = fmaf(S - m, VA, (float)(FF - 1) * VB);    // (v_sum - Qc)
    }
    __syncthreads();   // single block sync in the whole kernel

    // ---- Combine heads, broadcast over f ----
    float ox = ab, cc = ab;
    #pragma unroll
    for (int hh = 0; hh < HH; hh++) { ox += s_ox[hh]; cc += s_hc[hh]; }

    out[b * FF + t]                 = ox;
    out[b * FF + t + 256]           = ox;
    out[BB * FF + b * FF + t]       = cc;
    out[BB * FF + b * FF + t + 256] = cc;
}

extern "C" void kernel_launch(void* const* d_in, const int* in_sizes, int n_in,
                              void* d_out, int out_size) {
    const float* features = (const float*)d_in[0];
    const float* emb_w    = (const float*)d_in[1];
    const float* emb_b    = (const float*)d_in[2];
    const float* q_w      = (const float*)d_in[3];
    const float* q_b      = (const float*)d_in[4];
    const float* k_w      = (const float*)d_in[5];
    // d_in[6] = k_b: cancels in softmax, unused
    const float* v_w      = (const float*)d_in[7];
    const float* v_b      = (const float*)d_in[8];
    const float* attn_w   = (const float*)d_in[9];
    const float* attn_b   = (const float*)d_in[10];
    float* out = (float*)d_out;

    precompute_kernel<<<32, 256>>>(emb_w, emb_b, q_w, q_b, k_w, v_w, v_b);
    attn_kernel<<<BB, 256>>>(features, attn_w, attn_b, out);
}